// round 13
// baseline (speedup 1.0000x reference)
#include <cuda_runtime.h>
#include <cuda_fp16.h>
#include <cstdint>

#define NB 8
#define NTX 128
#define NTY 128
#define ND 512
#define NH 512
#define TYB 4

// Scratch (allocation-free rule: __device__ globals) — fp16
__device__ __half g_WcT[NB * NH * NTX];   // [b][h][tx]
__device__ __half g_UxT[NB * NH * NTY];   // [b][h][ty]

__device__ __forceinline__ uint32_t f2tf32(float x) {
    uint32_t r;
    asm("cvt.rna.tf32.f32 %0, %1;" : "=r"(r) : "f"(x));
    return r;
}

__device__ __forceinline__ void mma_tf32(float d[4], const uint32_t a[4],
                                         const uint32_t b[2]) {
    asm volatile(
        "mma.sync.aligned.m16n8k8.row.col.f32.tf32.tf32.f32 "
        "{%0,%1,%2,%3}, {%4,%5,%6,%7}, {%8,%9}, {%0,%1,%2,%3};"
        : "+f"(d[0]), "+f"(d[1]), "+f"(d[2]), "+f"(d[3])
        : "r"(a[0]), "r"(a[1]), "r"(a[2]), "r"(a[3]), "r"(b[0]), "r"(b[1]));
}

__device__ __forceinline__ __half2 htanh2(__half2 x) {
    uint32_t u = *reinterpret_cast<uint32_t*>(&x), t;
    asm("tanh.approx.f16x2 %0, %1;" : "=r"(t) : "r"(u));
    return *reinterpret_cast<__half2*>(&t);
}

__device__ __forceinline__ void cp_async16(uint32_t smem_addr, const void* gptr) {
    asm volatile("cp.async.cg.shared.global [%0], [%1], 16;"
                 :: "r"(smem_addr), "l"(gptr));
}

// ---------------------------------------------------------------------------
// Kernel 1 (tensor core, unchanged R10): OutT = A @ W + bias, fp16 transposed
// ---------------------------------------------------------------------------
__global__ void __launch_bounds__(256)
bahdanau_gemm_tc(const float* __restrict__ Ctx, const float* __restrict__ X,
                 const float* __restrict__ Wa, const float* __restrict__ bWa,
                 const float* __restrict__ Ua, const float* __restrict__ bUa)
{
    const int which = blockIdx.z >> 3;       // 0: Wc, 1: Ux
    const int b     = blockIdx.z & 7;
    const float* A    = (which ? X  : Ctx) + b * NTX * ND;   // [128][512]
    const float* W    =  which ? Ua : Wa;                    // [512][512]
    const float* bias =  which ? bUa : bWa;
    __half* OutT = (which ? g_UxT : g_WcT) + (size_t)b * NH * NTX;  // [512][128]

    const int h0 = blockIdx.x * 64;
    const int t0 = blockIdx.y * 64;

    __shared__ __align__(16) float pool[4480];               // 17.5 KB
    float (*As)[36]   = reinterpret_cast<float(*)[36]>(pool);          // [64][36]
    float (*Bs)[68]   = reinterpret_cast<float(*)[68]>(pool + 2304);   // [32][68]
    float (*Sout)[68] = reinterpret_cast<float(*)[68]>(pool);          // [64][68]

    const int tid  = threadIdx.x;
    const int warp = tid >> 5, lane = tid & 31;
    const int wm = warp >> 2, wn = warp & 3;    // 2x4 warp grid
    const int gid = lane >> 2, tq = lane & 3;

    const int arow = tid >> 2, ak = (tid & 3) * 8;   // A: 64 t-rows x 32 k
    const int brow = tid >> 3, bh = (tid & 7) * 8;   // B: 32 k-rows x 64 h

    const float* Abase = A + (t0 + arow) * ND + ak;
    const float* Bbase = W + brow * NH + h0 + bh;

    float4 pa[2], pb[2];
#pragma unroll
    for (int i = 0; i < 2; i++) pa[i] = *(const float4*)(Abase + i * 4);
#pragma unroll
    for (int i = 0; i < 2; i++) pb[i] = *(const float4*)(Bbase + i * 4);

    float acc[2][2][4];
#pragma unroll
    for (int mt = 0; mt < 2; mt++)
#pragma unroll
        for (int nt = 0; nt < 2; nt++)
#pragma unroll
            for (int r = 0; r < 4; r++) acc[mt][nt][r] = 0.f;

#pragma unroll 1
    for (int kc = 0; kc < 16; kc++) {
        __syncthreads();
#pragma unroll
        for (int i = 0; i < 2; i++) {
            float4 v = pa[i];
            uint4 u = make_uint4(f2tf32(v.x), f2tf32(v.y), f2tf32(v.z), f2tf32(v.w));
            *reinterpret_cast<uint4*>(&As[arow][ak + i * 4]) = u;
        }
#pragma unroll
        for (int i = 0; i < 2; i++) {
            float4 v = pb[i];
            uint4 u = make_uint4(f2tf32(v.x), f2tf32(v.y), f2tf32(v.z), f2tf32(v.w));
            *reinterpret_cast<uint4*>(&Bs[brow][bh + i * 4]) = u;
        }
        __syncthreads();

        if (kc < 15) {
            const float* an = Abase + (kc + 1) * 32;
            const float* bn = Bbase + (size_t)(kc + 1) * 32 * NH;
#pragma unroll
            for (int i = 0; i < 2; i++) pa[i] = *(const float4*)(an + i * 4);
#pragma unroll
            for (int i = 0; i < 2; i++) pb[i] = *(const float4*)(bn + i * 4);
        }

#pragma unroll
        for (int ks = 0; ks < 4; ks++) {
            const int kb = ks * 8;
            uint32_t af[2][4], bf[2][2];
#pragma unroll
            for (int mt = 0; mt < 2; mt++) {
                const int r = wm * 32 + mt * 16 + gid;
                af[mt][0] = __float_as_uint(As[r    ][kb + tq]);
                af[mt][1] = __float_as_uint(As[r + 8][kb + tq]);
                af[mt][2] = __float_as_uint(As[r    ][kb + tq + 4]);
                af[mt][3] = __float_as_uint(As[r + 8][kb + tq + 4]);
            }
#pragma unroll
            for (int nt = 0; nt < 2; nt++) {
                const int c = wn * 16 + nt * 8 + gid;
                bf[nt][0] = __float_as_uint(Bs[kb + tq    ][c]);
                bf[nt][1] = __float_as_uint(Bs[kb + tq + 4][c]);
            }
#pragma unroll
            for (int mt = 0; mt < 2; mt++)
#pragma unroll
                for (int nt = 0; nt < 2; nt++)
                    mma_tf32(acc[mt][nt], af[mt], bf[nt]);
        }
    }
    __syncthreads();

#pragma unroll
    for (int mt = 0; mt < 2; mt++)
#pragma unroll
        for (int nt = 0; nt < 2; nt++) {
            const int n = wn * 16 + nt * 8 + 2 * tq;
            const int m = wm * 32 + mt * 16 + gid;
            Sout[n    ][m    ] = acc[mt][nt][0];
            Sout[n + 1][m    ] = acc[mt][nt][1];
            Sout[n    ][m + 8] = acc[mt][nt][2];
            Sout[n + 1][m + 8] = acc[mt][nt][3];
        }
    __syncthreads();

    {
        const int row = tid >> 2;
        const int cg  = (tid & 3) * 16;
        const float bv = __ldg(&bias[h0 + row]);
        __half2 hx[8];
#pragma unroll
        for (int k = 0; k < 8; k++)
            hx[k] = __floats2half2_rn(Sout[row][cg + 2 * k] + bv,
                                      Sout[row][cg + 2 * k + 1] + bv);
        __half* orow = OutT + (size_t)(h0 + row) * NTX + t0 + cg;
        *reinterpret_cast<uint4*>(orow)     = *reinterpret_cast<uint4*>(hx);
        *reinterpret_cast<uint4*>(orow + 8) = *reinterpret_cast<uint4*>(hx + 4);
    }
}

// ---------------------------------------------------------------------------
// Kernel 2: fused scores + softmax + cv + LayerNorm + residual.
// Phase 1 streams WcT through double-buffered smem via cp.async (32-h chunks).
// 512 threads = 64 tx-pairs x 8 h-lanes; thread computes 4 h per chunk.
// ---------------------------------------------------------------------------
__global__ void __launch_bounds__(512, 2)
bahdanau_attn(const float* __restrict__ Ctx, const float* __restrict__ X,
              const float* __restrict__ Va, const float* __restrict__ gamma,
              const float* __restrict__ beta, float* __restrict__ out)
{
    const int b   = blockIdx.x >> 5;
    const int ty0 = (blockIdx.x & 31) * TYB;

    __shared__ __align__(16) __half2 ux2_s[NH * TYB];      //  8 KB: half2(u,u)
    __shared__ __align__(16) __half2 va2_s[NH];            //  2 KB: half2(v,v)
    __shared__ __align__(16) __half  wc_buf[2][32 * NTX];  // 16 KB: 2 x (32h x 128tx)
    __shared__ __align__(16) float   part[8 * TYB * NTX];  // 16 KB (cv overlay)
    __shared__ __align__(16) float   attn_s[TYB][NTX];     //  2 KB  => 44 KB

    const int tid = threadIdx.x;
    const __half* wc_src = g_WcT + (size_t)b * NH * NTX;   // 512x128 fp16

    // Prologue: start chunks 0 and 1 (16 B per thread each: 8 KB per chunk)
    {
        uint32_t s0 = (uint32_t)__cvta_generic_to_shared(&wc_buf[0][0]) + tid * 16;
        uint32_t s1 = (uint32_t)__cvta_generic_to_shared(&wc_buf[1][0]) + tid * 16;
        cp_async16(s0, (const char*)wc_src + tid * 16);
        asm volatile("cp.async.commit_group;");
        cp_async16(s1, (const char*)(wc_src + 32 * NTX) + tid * 16);
        asm volatile("cp.async.commit_group;");
    }

    // Stage Ux (one h per thread: 4 ty halfs = uint2) and Va (overlaps cp.async)
    {
        uint2 uv = *reinterpret_cast<const uint2*>(
            g_UxT + ((size_t)(b * NH + tid)) * NTY + ty0);
        const __half* up = reinterpret_cast<const __half*>(&uv);
#pragma unroll
        for (int j = 0; j < TYB; j++)
            ux2_s[tid * TYB + j] = __half2half2(up[j]);
        va2_s[tid] = __float2half2_rn(Va[tid]);
    }

    // ---- Phase 1: s[j][tx] = sum_h tanh(Wc[tx,h]+Ux[j,h]) * Va[h]
    {
        const int txp   = tid & 63;      // tx pair: tx = 2txp, 2txp+1
        const int hlane = tid >> 6;      // 0..7; h rows hlane*4..hlane*4+3 per chunk

        float sacc[TYB][2];
#pragma unroll
        for (int j = 0; j < TYB; j++) { sacc[j][0] = 0.f; sacc[j][1] = 0.f; }

#pragma unroll 1
        for (int c = 0; c < 16; c++) {
            if (c == 15) { asm volatile("cp.async.wait_group 0;"); }
            else         { asm volatile("cp.async.wait_group 1;"); }
            __syncthreads();   // chunk c visible to all

            const __half* buf = wc_buf[c & 1];
            __half2 acc2[TYB];
#pragma unroll
            for (int j = 0; j < TYB; j++)
                acc2[j] = __floats2half2_rn(0.f, 0.f);

#pragma unroll
            for (int i = 0; i < 4; i++) {
                const int hrow = hlane * 4 + i;        // row in chunk
                const int h    = c * 32 + hrow;        // global h
                const __half2 w2 = *reinterpret_cast<const __half2*>(
                    buf + hrow * NTX + 2 * txp);
                const __half2 v2 = va2_s[h];
                uint2 ua = *reinterpret_cast<const uint2*>(&ux2_s[h * TYB]);
                uint2 ub = *reinterpret_cast<const uint2*>(&ux2_s[h * TYB + 2]);
                const __half2* u = reinterpret_cast<const __half2*>(&ua);
                const __half2* v = reinterpret_cast<const __half2*>(&ub);
#pragma unroll
                for (int j = 0; j < 2; j++)
                    acc2[j] = __hfma2(htanh2(__hadd2(w2, u[j])), v2, acc2[j]);
#pragma unroll
                for (int j = 0; j < 2; j++)
                    acc2[2 + j] = __hfma2(htanh2(__hadd2(w2, v[j])), v2, acc2[2 + j]);
            }
            // flush fp16 chunk (4 h) to fp32
#pragma unroll
            for (int j = 0; j < TYB; j++) {
                float2 f = __half22float2(acc2[j]);
                sacc[j][0] += f.x;
                sacc[j][1] += f.y;
            }

            __syncthreads();   // all reads of buf[c&1] done before refill
            if (c + 2 < 16) {
                uint32_t sa = (uint32_t)__cvta_generic_to_shared(&wc_buf[c & 1][0])
                            + tid * 16;
                cp_async16(sa, (const char*)(wc_src + (size_t)(c + 2) * 32 * NTX)
                               + tid * 16);
            }
            asm volatile("cp.async.commit_group;");
        }

        // Write partials: group = hlane
#pragma unroll
        for (int j = 0; j < TYB; j++)
            *reinterpret_cast<float2*>(&part[(hlane * TYB + j) * NTX + 2 * txp]) =
                make_float2(sacc[j][0], sacc[j][1]);
    }
    __syncthreads();

    // ---- Phase 2: softmax over tx per ty row; warp j (j<4) handles row j.
    if (tid < 128) {
        const int j = tid >> 5, lane = tid & 31;
        float vals[4];
        float mx = -1e30f;
#pragma unroll
        for (int i = 0; i < 4; i++) {
            int t = lane + i * 32;
            float v = 0.f;
#pragma unroll
            for (int g = 0; g < 8; g++)
                v += part[(g * TYB + j) * NTX + t];
            vals[i] = v;
            mx = fmaxf(mx, v);
        }
#pragma unroll
        for (int off = 16; off; off >>= 1)
            mx = fmaxf(mx, __shfl_xor_sync(0xffffffffu, mx, off));
        float sum = 0.f;
#pragma unroll
        for (int i = 0; i < 4; i++) {
            vals[i] = __expf(vals[i] - mx);
            sum += vals[i];
        }
#pragma unroll
        for (int off = 16; off; off >>= 1)
            sum += __shfl_xor_sync(0xffffffffu, sum, off);
        float inv = __frcp_rn(sum);
#pragma unroll
        for (int i = 0; i < 4; i++)
            attn_s[j][lane + i * 32] = vals[i] * inv;
    }
    __syncthreads();

    // ---- Phase 3: cv[j][d] = sum_tx attn[j][tx] * context[b][tx][d]
    {
        const int d = tid;
        float acc[TYB];
#pragma unroll
        for (int j = 0; j < TYB; j++) acc[j] = 0.f;
        const float* cbase = Ctx + (size_t)b * NTX * ND + d;
#pragma unroll 1
        for (int t = 0; t < NTX; t += 8) {
            float c[8];
#pragma unroll
            for (int i = 0; i < 8; i++)
                c[i] = __ldg(cbase + (size_t)(t + i) * ND);
#pragma unroll
            for (int i = 0; i < 8; i++) {
#pragma unroll
                for (int j = 0; j < TYB; j++)
                    acc[j] += attn_s[j][t + i] * c[i];
            }
        }
#pragma unroll
        for (int j = 0; j < TYB; j++)
            part[j * ND + d] = acc[j];   // cv overlay: [TYB][ND]
    }
    __syncthreads();

    // ---- Phase 4: LayerNorm + residual. Warp j (j<4) handles row j.
    if (tid < 128) {
        const int j = tid >> 5, lane = tid & 31;
        float vals[16];
        float sum = 0.f;
#pragma unroll
        for (int i = 0; i < 16; i++) {
            int d = i * 32 + lane;
            vals[i] = part[j * ND + d];
            sum += vals[i];
        }
#pragma unroll
        for (int off = 16; off; off >>= 1)
            sum += __shfl_xor_sync(0xffffffffu, sum, off);
        const float mean = sum * (1.0f / ND);
        float vsum = 0.f;
#pragma unroll
        for (int i = 0; i < 16; i++) {
            float dlt = vals[i] - mean;
            vsum += dlt * dlt;
        }
#pragma unroll
        for (int off = 16; off; off >>= 1)
            vsum += __shfl_xor_sync(0xffffffffu, vsum, off);
        const float scale = rsqrtf(vsum * (1.0f / ND) + 1e-3f);

        const int ty = ty0 + j;
        const float* xr = X + ((size_t)b * NTY + ty) * ND;
        float* orow = out + ((size_t)b * NTY + ty) * ND;
#pragma unroll
        for (int i = 0; i < 16; i++) {
            int d = i * 32 + lane;
            orow[d] = (vals[i] - mean) * scale * gamma[d] + beta[d] + xr[d];
        }
    }
}

// ---------------------------------------------------------------------------
extern "C" void kernel_launch(void* const* d_in, const int* in_sizes, int n_in,
                              void* d_out, int out_size)
{
    const float* ctx   = (const float*)d_in[0];
    const float* x     = (const float*)d_in[1];
    const float* Wa    = (const float*)d_in[2];
    const float* bWa   = (const float*)d_in[3];
    const float* Ua    = (const float*)d_in[4];
    const float* bUa   = (const float*)d_in[5];
    const float* Va    = (const float*)d_in[6];
    // d_in[7] = bVa: scalar added to scores; cancels exactly in softmax.
    const float* gamma = (const float*)d_in[8];
    const float* beta  = (const float*)d_in[9];
    float* out = (float*)d_out;

    dim3 g1(NH / 64, NTX / 64, NB * 2);   // (8, 2, 16) = 256 blocks
    bahdanau_gemm_tc<<<g1, 256>>>(ctx, x, Wa, bWa, Ua, bUa);

    bahdanau_attn<<<NB * (NTY / TYB), 512>>>(ctx, x, Va, gamma, beta, out);
}

// round 14
// speedup vs baseline: 1.1573x; 1.1573x over previous
#include <cuda_runtime.h>
#include <cuda_fp16.h>
#include <cstdint>

#define NB 8
#define NTX 128
#define NTY 128
#define ND 512
#define NH 512
#define TYB 8

// Scratch (allocation-free rule: __device__ globals) — fp16
__device__ __half g_WcT[NB * NH * NTX];   // [b][h][tx]
__device__ __half g_UxT[NB * NH * NTY];   // [b][h][ty]

__device__ __forceinline__ void mma_f16(float d[4], const uint32_t a[4],
                                        const uint32_t b[2]) {
    asm volatile(
        "mma.sync.aligned.m16n8k16.row.col.f32.f16.f16.f32 "
        "{%0,%1,%2,%3}, {%4,%5,%6,%7}, {%8,%9}, {%0,%1,%2,%3};"
        : "+f"(d[0]), "+f"(d[1]), "+f"(d[2]), "+f"(d[3])
        : "r"(a[0]), "r"(a[1]), "r"(a[2]), "r"(a[3]), "r"(b[0]), "r"(b[1]));
}

__device__ __forceinline__ __half2 htanh2(__half2 x) {
    uint32_t u = *reinterpret_cast<uint32_t*>(&x), t;
    asm("tanh.approx.f16x2 %0, %1;" : "=r"(t) : "r"(u));
    return *reinterpret_cast<__half2*>(&t);
}

// ---------------------------------------------------------------------------
// Kernel 1 (fp16 HMMA): OutT[b][h][t] = sum_d A[b][t][d]*W[d][h] + bias[h]
// Tile 64(t) x 64(h), 256 threads (2x4 warp grid), K chunks of 32 (2 k16
// mma steps), register prefetch, fp16 smem tiles, fp16 output.
// Grid (8, 2, 16) = 256 blocks.
// ---------------------------------------------------------------------------
__global__ void __launch_bounds__(256)
bahdanau_gemm_tc(const float* __restrict__ Ctx, const float* __restrict__ X,
                 const float* __restrict__ Wa, const float* __restrict__ bWa,
                 const float* __restrict__ Ua, const float* __restrict__ bUa)
{
    const int which = blockIdx.z >> 3;       // 0: Wc, 1: Ux
    const int b     = blockIdx.z & 7;
    const float* A    = (which ? X  : Ctx) + b * NTX * ND;   // [128][512]
    const float* W    =  which ? Ua : Wa;                    // [512][512]
    const float* bias =  which ? bUa : bWa;
    __half* OutT = (which ? g_UxT : g_WcT) + (size_t)b * NH * NTX;  // [512][128]

    const int h0 = blockIdx.x * 64;
    const int t0 = blockIdx.y * 64;

    // smem: As [64][40] halfs (5120 B), Bs [64][34] halfs (4352 B),
    // Sout [64][68] floats (17408 B) overlays both after the mainloop.
    __shared__ __align__(16) char smem_raw[17408];
    __half (*As)[40]   = reinterpret_cast<__half(*)[40]>(smem_raw);
    __half (*Bs)[34]   = reinterpret_cast<__half(*)[34]>(smem_raw + 5120);
    float (*Sout)[68]  = reinterpret_cast<float(*)[68]>(smem_raw);

    const int tid  = threadIdx.x;
    const int warp = tid >> 5, lane = tid & 31;
    const int wm = warp >> 2, wn = warp & 3;    // 2x4 warp grid
    const int gid = lane >> 2, tq = lane & 3;

    // loader indexing (256 threads)
    const int arow = tid >> 2, ak = (tid & 3) * 8;   // A: 64 t-rows x 32 k
    const int brow = tid >> 3, bh = (tid & 7) * 8;   // B: 32 k-rows x 64 h

    const float* Abase = A + (t0 + arow) * ND + ak;
    const float* Bbase = W + brow * NH + h0 + bh;

    float4 pa[2], pb[2];
#pragma unroll
    for (int i = 0; i < 2; i++) pa[i] = *(const float4*)(Abase + i * 4);
#pragma unroll
    for (int i = 0; i < 2; i++) pb[i] = *(const float4*)(Bbase + i * 4);

    float acc[2][2][4];
#pragma unroll
    for (int mt = 0; mt < 2; mt++)
#pragma unroll
        for (int nt = 0; nt < 2; nt++)
#pragma unroll
            for (int r = 0; r < 4; r++) acc[mt][nt][r] = 0.f;

#pragma unroll 1
    for (int kc = 0; kc < 16; kc++) {
        __syncthreads();
        {   // A tile: pack 8 fp32 -> 8 fp16 -> one 16B STS (aligned: 80B rows)
            __half2 h2[4];
            h2[0] = __floats2half2_rn(pa[0].x, pa[0].y);
            h2[1] = __floats2half2_rn(pa[0].z, pa[0].w);
            h2[2] = __floats2half2_rn(pa[1].x, pa[1].y);
            h2[3] = __floats2half2_rn(pa[1].z, pa[1].w);
            *reinterpret_cast<uint4*>(&As[arow][ak]) =
                *reinterpret_cast<uint4*>(h2);
        }
        {   // B tile: transpose scatter — Bs[h][k], 8 x 2-byte STS
            const float* pf = reinterpret_cast<const float*>(pb);
#pragma unroll
            for (int i = 0; i < 8; i++)
                Bs[bh + i][brow] = __float2half_rn(pf[i]);
        }
        __syncthreads();

        if (kc < 15) {   // prefetch next K chunk (overlaps mma)
            const float* an = Abase + (kc + 1) * 32;
            const float* bn = Bbase + (size_t)(kc + 1) * 32 * NH;
#pragma unroll
            for (int i = 0; i < 2; i++) pa[i] = *(const float4*)(an + i * 4);
#pragma unroll
            for (int i = 0; i < 2; i++) pb[i] = *(const float4*)(bn + i * 4);
        }

#pragma unroll
        for (int ks = 0; ks < 2; ks++) {
            const int kb = ks * 16;
            uint32_t af[2][4], bf[2][2];
#pragma unroll
            for (int mt = 0; mt < 2; mt++) {
                const int r = wm * 32 + mt * 16 + gid;
                af[mt][0] = *reinterpret_cast<const uint32_t*>(&As[r    ][kb + 2 * tq]);
                af[mt][1] = *reinterpret_cast<const uint32_t*>(&As[r + 8][kb + 2 * tq]);
                af[mt][2] = *reinterpret_cast<const uint32_t*>(&As[r    ][kb + 2 * tq + 8]);
                af[mt][3] = *reinterpret_cast<const uint32_t*>(&As[r + 8][kb + 2 * tq + 8]);
            }
#pragma unroll
            for (int nt = 0; nt < 2; nt++) {
                const int c = wn * 16 + nt * 8 + gid;
                bf[nt][0] = *reinterpret_cast<const uint32_t*>(&Bs[c][kb + 2 * tq]);
                bf[nt][1] = *reinterpret_cast<const uint32_t*>(&Bs[c][kb + 2 * tq + 8]);
            }
#pragma unroll
            for (int mt = 0; mt < 2; mt++)
#pragma unroll
                for (int nt = 0; nt < 2; nt++)
                    mma_f16(acc[mt][nt], af[mt], bf[nt]);
        }
    }
    __syncthreads();

    // Transpose via smem: Sout[n(h)][m(t)] (accum layout same as tf32 m16n8)
#pragma unroll
    for (int mt = 0; mt < 2; mt++)
#pragma unroll
        for (int nt = 0; nt < 2; nt++) {
            const int n = wn * 16 + nt * 8 + 2 * tq;
            const int m = wm * 32 + mt * 16 + gid;
            Sout[n    ][m    ] = acc[mt][nt][0];
            Sout[n + 1][m    ] = acc[mt][nt][1];
            Sout[n    ][m + 8] = acc[mt][nt][2];
            Sout[n + 1][m + 8] = acc[mt][nt][3];
        }
    __syncthreads();

    // fp16 pack + store: 64 h-rows x 64 t. 256 threads: 16 t per thread.
    {
        const int row = tid >> 2;
        const int cg  = (tid & 3) * 16;
        const float bv = __ldg(&bias[h0 + row]);
        __half2 hx[8];
#pragma unroll
        for (int k = 0; k < 8; k++)
            hx[k] = __floats2half2_rn(Sout[row][cg + 2 * k] + bv,
                                      Sout[row][cg + 2 * k + 1] + bv);
        __half* orow = OutT + (size_t)(h0 + row) * NTX + t0 + cg;
        *reinterpret_cast<uint4*>(orow)     = *reinterpret_cast<uint4*>(hx);
        *reinterpret_cast<uint4*>(orow + 8) = *reinterpret_cast<uint4*>(hx + 4);
    }
}

// ---------------------------------------------------------------------------
// Kernel 2 (R10 best-measured, 32.3 us): fused scores + softmax + cv + LN +
// residual. TYB=8, grid 128, packed fp16 phase 1, depth-8 prefetch.
// ---------------------------------------------------------------------------
__global__ void __launch_bounds__(512, 2)
bahdanau_attn(const float* __restrict__ Ctx, const float* __restrict__ X,
              const float* __restrict__ Va, const float* __restrict__ gamma,
              const float* __restrict__ beta, float* __restrict__ out)
{
    const int b   = blockIdx.x >> 4;
    const int ty0 = (blockIdx.x & 15) * TYB;

    __shared__ __align__(16) __half2 ux2_s[NH * TYB];    // 16 KB: half2(u,u)
    __shared__ __align__(16) __half2 va2_s[NH];          //  2 KB: half2(v,v)
    __shared__ __align__(16) float  part[8 * TYB * NTX]; // 32 KB (cv overlay)
    __shared__ __align__(16) float  attn_s[TYB][NTX];    //  4 KB

    const int tid = threadIdx.x;

    // Stage Ux (one h per thread: 8 ty halfs = uint4) and Va
    {
        uint4 uv = *reinterpret_cast<const uint4*>(
            g_UxT + ((size_t)(b * NH + tid)) * NTY + ty0);
        const __half* up = reinterpret_cast<const __half*>(&uv);
#pragma unroll
        for (int j = 0; j < TYB; j++)
            ux2_s[tid * TYB + j] = __half2half2(up[j]);
        va2_s[tid] = __float2half2_rn(Va[tid]);
    }
    __syncthreads();

    // ---- Phase 1: s[j][tx] = sum_h tanh(Wc[tx,h]+Ux[j,h]) * Va[h]
    {
        const int txp = tid & 63;        // tx pair: tx = 2txp, 2txp+1
        const int g   = tid >> 6;        // h-group: h in [g*64, g*64+64)

        float sacc[TYB][2];
#pragma unroll
        for (int j = 0; j < TYB; j++) { sacc[j][0] = 0.f; sacc[j][1] = 0.f; }

        const __half2* wp = reinterpret_cast<const __half2*>(g_WcT)
                          + (size_t)(b * NH + g * 64) * (NTX / 2) + txp;

        uint32_t wr[8];
#pragma unroll
        for (int i = 0; i < 8; i++)
            wr[i] = __ldg(reinterpret_cast<const uint32_t*>(wp + i * 64));

#pragma unroll 1
        for (int hh = 0; hh < 64; hh += 4) {
            __half2 acc2[TYB];
#pragma unroll
            for (int j = 0; j < TYB; j++)
                acc2[j] = __floats2half2_rn(0.f, 0.f);

#pragma unroll
            for (int i = 0; i < 4; i++) {
                const int h = g * 64 + hh + i;
                const __half2 w2 = *reinterpret_cast<const __half2*>(&wr[i]);
                const __half2 v2 = va2_s[h];
                uint4 ua = *reinterpret_cast<const uint4*>(&ux2_s[h * 8]);
                uint4 ub = *reinterpret_cast<const uint4*>(&ux2_s[h * 8 + 4]);
                const __half2* u = reinterpret_cast<const __half2*>(&ua);
                const __half2* v = reinterpret_cast<const __half2*>(&ub);
#pragma unroll
                for (int j = 0; j < 4; j++)
                    acc2[j] = __hfma2(htanh2(__hadd2(w2, u[j])), v2, acc2[j]);
#pragma unroll
                for (int j = 0; j < 4; j++)
                    acc2[4 + j] = __hfma2(htanh2(__hadd2(w2, v[j])), v2, acc2[4 + j]);
            }
#pragma unroll
            for (int j = 0; j < TYB; j++) {
                float2 f = __half22float2(acc2[j]);
                sacc[j][0] += f.x;
                sacc[j][1] += f.y;
            }
#pragma unroll
            for (int i = 0; i < 4; i++) wr[i] = wr[i + 4];
            if (hh + 8 < 64) {
#pragma unroll
                for (int i = 0; i < 4; i++)
                    wr[4 + i] = __ldg(reinterpret_cast<const uint32_t*>(
                        wp + (hh + 8 + i) * 64));
            }
        }

#pragma unroll
        for (int j = 0; j < TYB; j++)
            *reinterpret_cast<float2*>(&part[(g * TYB + j) * NTX + 2 * txp]) =
                make_float2(sacc[j][0], sacc[j][1]);
    }
    __syncthreads();

    // ---- Phase 2: softmax over tx per ty row; warp j (j<8) handles row j.
    if (tid < 256) {
        const int j = tid >> 5, lane = tid & 31;
        float vals[4];
        float mx = -1e30f;
#pragma unroll
        for (int i = 0; i < 4; i++) {
            int t = lane + i * 32;
            float v = 0.f;
#pragma unroll
            for (int g = 0; g < 8; g++)
                v += part[(g * TYB + j) * NTX + t];
            vals[i] = v;
            mx = fmaxf(mx, v);
        }
#pragma unroll
        for (int off = 16; off; off >>= 1)
            mx = fmaxf(mx, __shfl_xor_sync(0xffffffffu, mx, off));
        float sum = 0.f;
#pragma unroll
        for (int i = 0; i < 4; i++) {
            vals[i] = __expf(vals[i] - mx);
            sum += vals[i];
        }
#pragma unroll
        for (int off = 16; off; off >>= 1)
            sum += __shfl_xor_sync(0xffffffffu, sum, off);
        float inv = __frcp_rn(sum);
#pragma unroll
        for (int i = 0; i < 4; i++)
            attn_s[j][lane + i * 32] = vals[i] * inv;
    }
    __syncthreads();

    // ---- Phase 3: cv[j][d] = sum_tx attn[j][tx] * context[b][tx][d]
    {
        const int g2 = tid >> 8;
        const int l  = tid & 255;
        const int d0 = l * 2;
        float acc[TYB][2];
#pragma unroll
        for (int j = 0; j < TYB; j++) { acc[j][0] = 0.f; acc[j][1] = 0.f; }
        const float* cbase = Ctx + (size_t)b * NTX * ND + (size_t)(g2 * 64) * ND + d0;
#pragma unroll 1
        for (int t = 0; t < 64; t += 8) {
            float2 c[8];
#pragma unroll
            for (int i = 0; i < 8; i++)
                c[i] = *reinterpret_cast<const float2*>(cbase + (size_t)(t + i) * ND);
#pragma unroll
            for (int i = 0; i < 8; i++) {
                const int tt = g2 * 64 + t + i;
#pragma unroll
                for (int j = 0; j < TYB; j++) {
                    float a = attn_s[j][tt];
                    acc[j][0] += a * c[i].x;
                    acc[j][1] += a * c[i].y;
                }
            }
        }
#pragma unroll
        for (int j = 0; j < TYB; j++) {
            part[g2 * 4096 + j * 512 + d0]     = acc[j][0];  // cvp overlay
            part[g2 * 4096 + j * 512 + d0 + 1] = acc[j][1];
        }
    }
    __syncthreads();

    // ---- Phase 4: LayerNorm + residual. Warp j (j<8) handles row j.
    if (tid < 256) {
        const int j = tid >> 5, lane = tid & 31;
        float vals[16];
        float sum = 0.f;
#pragma unroll
        for (int i = 0; i < 16; i++) {
            int d = i * 32 + lane;
            vals[i] = part[j * 512 + d] + part[4096 + j * 512 + d];
            sum += vals[i];
        }
#pragma unroll
        for (int off = 16; off; off >>= 1)
            sum += __shfl_xor_sync(0xffffffffu, sum, off);
        const float mean = sum * (1.0f / ND);
        float vsum = 0.f;
#pragma unroll
        for (int i = 0; i < 16; i++) {
            float dlt = vals[i] - mean;
            vsum += dlt * dlt;
        }
#pragma unroll
        for (int off = 16; off; off >>= 1)
            vsum += __shfl_xor_sync(0xffffffffu, vsum, off);
        const float scale = rsqrtf(vsum * (1.0f / ND) + 1e-3f);

        const int ty = ty0 + j;
        const float* xr = X + ((size_t)b * NTY + ty) * ND;
        float* orow = out + ((size_t)b * NTY + ty) * ND;
#pragma unroll
        for (int i = 0; i < 16; i++) {
            int d = i * 32 + lane;
            orow[d] = (vals[i] - mean) * scale * gamma[d] + beta[d] + xr[d];
        }
    }
}

// ---------------------------------------------------------------------------
extern "C" void kernel_launch(void* const* d_in, const int* in_sizes, int n_in,
                              void* d_out, int out_size)
{
    const float* ctx   = (const float*)d_in[0];
    const float* x     = (const float*)d_in[1];
    const float* Wa    = (const float*)d_in[2];
    const float* bWa   = (const float*)d_in[3];
    const float* Ua    = (const float*)d_in[4];
    const float* bUa   = (const float*)d_in[5];
    const float* Va    = (const float*)d_in[6];
    // d_in[7] = bVa: scalar added to scores; cancels exactly in softmax.
    const float* gamma = (const float*)d_in[8];
    const float* beta  = (const float*)d_in[9];
    float* out = (float*)d_out;

    dim3 g1(NH / 64, NTX / 64, NB * 2);   // (8, 2, 16) = 256 blocks
    bahdanau_gemm_tc<<<g1, 256>>>(ctx, x, Wa, bWa, Ua, bUa);

    bahdanau_attn<<<NB * (NTY / TYB), 512>>>(ctx, x, Va, gamma, beta, out);
}